// round 8
// baseline (speedup 1.0000x reference)
#include <cuda_runtime.h>

#define DD 128
#define NODES_MAX 50000

// Scratch: aggregated neighbor features (allocation-free rule -> __device__ global)
__device__ float g_agg[NODES_MAX * DD];

// ---------------------------------------------------------------------------
// Kernel 2: scatter-add  agg[dst] += x[src]
// Grid sized for ONE batch per warp; each warp processes EPW=16 edges:
//  - 32 broadcast index loads hoisted
//  - 16 independent LDG.128 row-gathers in flight (MLP=16)
//  - 16 float4 RED atomics (fire-and-forget)
// ---------------------------------------------------------------------------
#define EPW 16   // edges per warp-batch

__global__ __launch_bounds__(256)
void scatter_add_kernel(const float* __restrict__ x,
                        const int* __restrict__ src,
                        const int* __restrict__ dst,
                        int n_edges, int n_nodes) {
    const int lane = threadIdx.x & 31;
    const int gwarp = (blockIdx.x * blockDim.x + threadIdx.x) >> 5;
    const int nwarps = (gridDim.x * blockDim.x) >> 5;

    for (int base = gwarp * EPW; base < n_edges; base += nwarps * EPW) {
        const int cnt = min(EPW, n_edges - base);

        int s[EPW], d[EPW];
        #pragma unroll
        for (int i = 0; i < EPW; i++) {
            int e = (i < cnt) ? (base + i) : base;
            s[i] = __ldg(&src[e]);   // broadcast (1 sector)
            d[i] = __ldg(&dst[e]);
            if ((unsigned)s[i] >= (unsigned)n_nodes) s[i] = 0;  // fail-soft
        }

        float4 v[EPW];
        #pragma unroll
        for (int i = 0; i < EPW; i++) {
            v[i] = __ldg(reinterpret_cast<const float4*>(
                       x + (size_t)s[i] * DD) + lane);
        }

        #pragma unroll
        for (int i = 0; i < EPW; i++) {
            if (i < cnt && (unsigned)d[i] < (unsigned)n_nodes) {
                atomicAdd(reinterpret_cast<float4*>(
                              g_agg + (size_t)d[i] * DD) + lane, v[i]);
            }
        }
    }
}

// ---------------------------------------------------------------------------
// Kernel 3: out = relu(agg @ W^T) + x   with packed fma.rn.f32x2
// ---------------------------------------------------------------------------
#define WT_LD 132
#define WARPS_PER_BLOCK 8
#define ROWS_PER_WARP 4

__device__ __forceinline__ unsigned long long pack_dup(float b) {
    unsigned long long r;
    asm("mov.b64 %0, {%1, %1};" : "=l"(r) : "f"(b));
    return r;
}
__device__ __forceinline__ void fma2(unsigned long long& acc,
                                     unsigned long long a,
                                     unsigned long long b) {
    asm("fma.rn.f32x2 %0, %1, %2, %0;" : "+l"(acc) : "l"(a), "l"(b));
}
__device__ __forceinline__ float2 unpack2(unsigned long long v) {
    float lo, hi;
    asm("mov.b64 {%0, %1}, %2;" : "=f"(lo), "=f"(hi) : "l"(v));
    return make_float2(lo, hi);
}

__global__ __launch_bounds__(256)
void gemm_relu_res_kernel(const float* __restrict__ x,
                          const float* __restrict__ W,
                          float* __restrict__ out,
                          int n_rows) {
    extern __shared__ float smem[];
    float* Wt = smem;                              // [128][WT_LD]
    float* rowbuf = smem + DD * WT_LD;             // [WARPS][4][128]

    for (int idx = threadIdx.x; idx < DD * DD; idx += blockDim.x) {
        int j = idx & (DD - 1);
        int k = idx >> 7;
        Wt[k * WT_LD + j] = W[j * DD + k];
    }
    __syncthreads();

    const int warp = threadIdx.x >> 5;
    const int lane = threadIdx.x & 31;
    float* rb = rowbuf + warp * (ROWS_PER_WARP * DD);

    const int warps_total = gridDim.x * WARPS_PER_BLOCK;
    const int gwarp = blockIdx.x * WARPS_PER_BLOCK + warp;

    for (int r0 = gwarp * ROWS_PER_WARP; r0 < n_rows;
         r0 += warps_total * ROWS_PER_WARP) {

        __syncwarp();
        #pragma unroll
        for (int r = 0; r < ROWS_PER_WARP; r++) {
            int row = r0 + r;
            if (row < n_rows) {
                float4 v = *reinterpret_cast<const float4*>(
                    g_agg + (size_t)row * DD + lane * 4);
                *reinterpret_cast<float4*>(rb + r * DD + lane * 4) = v;
            }
        }
        __syncwarp();

        unsigned long long acc01[ROWS_PER_WARP] = {0ull, 0ull, 0ull, 0ull};
        unsigned long long acc23[ROWS_PER_WARP] = {0ull, 0ull, 0ull, 0ull};

        #pragma unroll 4
        for (int k = 0; k < DD; k += 4) {
            float4 a0 = *reinterpret_cast<const float4*>(rb + 0 * DD + k);
            float4 a1 = *reinterpret_cast<const float4*>(rb + 1 * DD + k);
            float4 a2 = *reinterpret_cast<const float4*>(rb + 2 * DD + k);
            float4 a3 = *reinterpret_cast<const float4*>(rb + 3 * DD + k);
            const float* pa[4] = {
                reinterpret_cast<const float*>(&a0),
                reinterpret_cast<const float*>(&a1),
                reinterpret_cast<const float*>(&a2),
                reinterpret_cast<const float*>(&a3)};

            #pragma unroll
            for (int kk = 0; kk < 4; kk++) {
                ulonglong2 w = *reinterpret_cast<const ulonglong2*>(
                    Wt + (k + kk) * WT_LD + lane * 4);
                #pragma unroll
                for (int r = 0; r < ROWS_PER_WARP; r++) {
                    unsigned long long bb = pack_dup(pa[r][kk]);
                    fma2(acc01[r], w.x, bb);
                    fma2(acc23[r], w.y, bb);
                }
            }
        }

        #pragma unroll
        for (int r = 0; r < ROWS_PER_WARP; r++) {
            int row = r0 + r;
            if (row >= n_rows) break;
            float2 p01 = unpack2(acc01[r]);
            float2 p23 = unpack2(acc23[r]);
            float4 xr = *reinterpret_cast<const float4*>(
                x + (size_t)row * DD + lane * 4);
            float4 res;
            res.x = fmaxf(p01.x, 0.f) + xr.x;
            res.y = fmaxf(p01.y, 0.f) + xr.y;
            res.z = fmaxf(p23.x, 0.f) + xr.z;
            res.w = fmaxf(p23.y, 0.f) + xr.w;
            *reinterpret_cast<float4*>(out + (size_t)row * DD + lane * 4) = res;
        }
    }
}

// ---------------------------------------------------------------------------
// Launch
// ---------------------------------------------------------------------------
extern "C" void kernel_launch(void* const* d_in, const int* in_sizes, int n_in,
                              void* d_out, int out_size) {
    const float* x   = (const float*)d_in[0];      // [N, 128] f32
    const float* W   = (const float*)d_in[1];      // [128, 128] f32
    const int*   src = (const int*)d_in[2];        // [E] int32
    const int*   dst = (const int*)d_in[3];        // [E] int32
    float*       out = (float*)d_out;              // [N, 128] f32

    const int n_nodes = in_sizes[0] / DD;
    const int n_edges = in_sizes[2];

    // 1) zero agg via graph-native memset node (full write bandwidth)
    void* agg_ptr = nullptr;
    cudaGetSymbolAddress(&agg_ptr, g_agg);
    cudaMemsetAsync(agg_ptr, 0, (size_t)n_nodes * DD * sizeof(float), 0);

    // 2) scatter-add: 16 edges per warp, one batch per warp (single pass)
    int nwarps_needed = (n_edges + EPW - 1) / EPW;            // 50000
    int blocks = (nwarps_needed + 7) / 8;                     // 8 warps/block
    scatter_add_kernel<<<blocks, 256>>>(x, src, dst, n_edges, n_nodes);

    // 3) fused GEMM + relu + residual (f32x2 packed FMA)
    size_t smem = (DD * WT_LD + WARPS_PER_BLOCK * ROWS_PER_WARP * DD) * sizeof(float);
    cudaFuncSetAttribute(gemm_relu_res_kernel,
                         cudaFuncAttributeMaxDynamicSharedMemorySize, (int)smem);
    gemm_relu_res_kernel<<<296, 256, smem>>>(x, W, out, n_nodes);
}

// round 9
// speedup vs baseline: 1.0167x; 1.0167x over previous
#include <cuda_runtime.h>

#define DD 128
#define NODES_MAX 50000

// Scratch: aggregated neighbor features (allocation-free rule -> __device__ global)
__device__ float g_agg[NODES_MAX * DD];

// ---------------------------------------------------------------------------
// Scatter-add  agg[dst] += x[src]
// Grid-stride; each warp processes batches of 8 edges (measured-best config):
//  - 16 broadcast index loads hoisted
//  - 8 independent LDG.128 row-gathers in flight
//  - 8 float4 RED atomics (fire-and-forget)
// ---------------------------------------------------------------------------
#define EPW 8

__global__ __launch_bounds__(256)
void scatter_add_kernel(const float* __restrict__ x,
                        const int* __restrict__ src,
                        const int* __restrict__ dst,
                        int n_edges, int n_nodes) {
    const int lane = threadIdx.x & 31;
    const int gwarp = (blockIdx.x * blockDim.x + threadIdx.x) >> 5;
    const int nwarps = (gridDim.x * blockDim.x) >> 5;

    for (int base = gwarp * EPW; base < n_edges; base += nwarps * EPW) {
        const int cnt = min(EPW, n_edges - base);

        int s[EPW], d[EPW];
        #pragma unroll
        for (int i = 0; i < EPW; i++) {
            int e = (i < cnt) ? (base + i) : base;
            s[i] = __ldg(&src[e]);
            d[i] = __ldg(&dst[e]);
            if ((unsigned)s[i] >= (unsigned)n_nodes) s[i] = 0;  // fail-soft
        }

        float4 v[EPW];
        #pragma unroll
        for (int i = 0; i < EPW; i++) {
            v[i] = __ldg(reinterpret_cast<const float4*>(
                       x + (size_t)s[i] * DD) + lane);
        }

        #pragma unroll
        for (int i = 0; i < EPW; i++) {
            if (i < cnt && (unsigned)d[i] < (unsigned)n_nodes) {
                atomicAdd(reinterpret_cast<float4*>(
                              g_agg + (size_t)d[i] * DD) + lane, v[i]);
            }
        }
    }
}

// ---------------------------------------------------------------------------
// GEMM: out = relu(agg @ W^T) + x   with packed fma.rn.f32x2
// ROWS_PER_WARP=8: halves per-row w-LDS traffic (the measured bottleneck:
// L1=79.6% in R8). Each warp streams Wt once per 8 output rows.
// ---------------------------------------------------------------------------
#define WT_LD 132
#define WARPS_PER_BLOCK 8
#define ROWS_PER_WARP 8

__device__ __forceinline__ unsigned long long pack_dup(float b) {
    unsigned long long r;
    asm("mov.b64 %0, {%1, %1};" : "=l"(r) : "f"(b));
    return r;
}
__device__ __forceinline__ void fma2(unsigned long long& acc,
                                     unsigned long long a,
                                     unsigned long long b) {
    asm("fma.rn.f32x2 %0, %1, %2, %0;" : "+l"(acc) : "l"(a), "l"(b));
}
__device__ __forceinline__ float2 unpack2(unsigned long long v) {
    float lo, hi;
    asm("mov.b64 {%0, %1}, %2;" : "=f"(lo), "=f"(hi) : "l"(v));
    return make_float2(lo, hi);
}

__global__ __launch_bounds__(256)
void gemm_relu_res_kernel(const float* __restrict__ x,
                          const float* __restrict__ W,
                          float* __restrict__ out,
                          int n_rows) {
    extern __shared__ float smem[];
    float* Wt = smem;                              // [128][WT_LD]
    float* rowbuf = smem + DD * WT_LD;             // [WARPS][8][128]

    for (int idx = threadIdx.x; idx < DD * DD; idx += blockDim.x) {
        int j = idx & (DD - 1);
        int k = idx >> 7;
        Wt[k * WT_LD + j] = W[j * DD + k];
    }
    __syncthreads();

    const int warp = threadIdx.x >> 5;
    const int lane = threadIdx.x & 31;
    float* rb = rowbuf + warp * (ROWS_PER_WARP * DD);

    const int warps_total = gridDim.x * WARPS_PER_BLOCK;
    const int gwarp = blockIdx.x * WARPS_PER_BLOCK + warp;

    for (int r0 = gwarp * ROWS_PER_WARP; r0 < n_rows;
         r0 += warps_total * ROWS_PER_WARP) {

        __syncwarp();
        #pragma unroll
        for (int r = 0; r < ROWS_PER_WARP; r++) {
            int row = r0 + r;
            if (row < n_rows) {
                float4 v = *reinterpret_cast<const float4*>(
                    g_agg + (size_t)row * DD + lane * 4);
                *reinterpret_cast<float4*>(rb + r * DD + lane * 4) = v;
            }
        }
        __syncwarp();

        // acc per row: {cols lane*4, lane*4+1} and {lane*4+2, lane*4+3}
        unsigned long long acc01[ROWS_PER_WARP];
        unsigned long long acc23[ROWS_PER_WARP];
        #pragma unroll
        for (int r = 0; r < ROWS_PER_WARP; r++) { acc01[r] = 0ull; acc23[r] = 0ull; }

        #pragma unroll 2
        for (int k = 0; k < DD; k += 4) {
            // 8 broadcast a-vectors (LDS.128, N=1 -> cheap)
            float4 a[ROWS_PER_WARP];
            #pragma unroll
            for (int r = 0; r < ROWS_PER_WARP; r++)
                a[r] = *reinterpret_cast<const float4*>(rb + r * DD + k);
            const float* pa[ROWS_PER_WARP];
            #pragma unroll
            for (int r = 0; r < ROWS_PER_WARP; r++)
                pa[r] = reinterpret_cast<const float*>(&a[r]);

            #pragma unroll
            for (int kk = 0; kk < 4; kk++) {
                ulonglong2 w = *reinterpret_cast<const ulonglong2*>(
                    Wt + (k + kk) * WT_LD + lane * 4);
                #pragma unroll
                for (int r = 0; r < ROWS_PER_WARP; r++) {
                    unsigned long long bb = pack_dup(pa[r][kk]);
                    fma2(acc01[r], w.x, bb);
                    fma2(acc23[r], w.y, bb);
                }
            }
        }

        #pragma unroll
        for (int r = 0; r < ROWS_PER_WARP; r++) {
            int row = r0 + r;
            if (row >= n_rows) break;
            float2 p01 = unpack2(acc01[r]);
            float2 p23 = unpack2(acc23[r]);
            float4 xr = *reinterpret_cast<const float4*>(
                x + (size_t)row * DD + lane * 4);
            float4 res;
            res.x = fmaxf(p01.x, 0.f) + xr.x;
            res.y = fmaxf(p01.y, 0.f) + xr.y;
            res.z = fmaxf(p23.x, 0.f) + xr.z;
            res.w = fmaxf(p23.y, 0.f) + xr.w;
            *reinterpret_cast<float4*>(out + (size_t)row * DD + lane * 4) = res;
        }
    }
}

// ---------------------------------------------------------------------------
// Launch
// ---------------------------------------------------------------------------
extern "C" void kernel_launch(void* const* d_in, const int* in_sizes, int n_in,
                              void* d_out, int out_size) {
    const float* x   = (const float*)d_in[0];      // [N, 128] f32
    const float* W   = (const float*)d_in[1];      // [128, 128] f32
    const int*   src = (const int*)d_in[2];        // [E] int32
    const int*   dst = (const int*)d_in[3];        // [E] int32
    float*       out = (float*)d_out;              // [N, 128] f32

    const int n_nodes = in_sizes[0] / DD;
    const int n_edges = in_sizes[2];

    // 1) zero agg via graph-native memset node
    void* agg_ptr = nullptr;
    cudaGetSymbolAddress(&agg_ptr, g_agg);
    cudaMemsetAsync(agg_ptr, 0, (size_t)n_nodes * DD * sizeof(float), 0);

    // 2) scatter-add, EPW=8, ~2 batches per warp (measured-best R7 config)
    int nwarps_needed = (n_edges + EPW - 1) / EPW;
    int blocks = (nwarps_needed / 2 + 7) / 8;
    if (blocks > 6144) blocks = 6144;
    if (blocks < 148) blocks = 148;
    scatter_add_kernel<<<blocks, 256>>>(x, src, dst, n_edges, n_nodes);

    // 3) fused GEMM + relu + residual (f32x2, 8 rows/warp)
    size_t smem = (DD * WT_LD + WARPS_PER_BLOCK * ROWS_PER_WARP * DD) * sizeof(float);
    cudaFuncSetAttribute(gemm_relu_res_kernel,
                         cudaFuncAttributeMaxDynamicSharedMemorySize, (int)smem);
    gemm_relu_res_kernel<<<296, 256, smem>>>(x, W, out, n_nodes);
}